// round 3
// baseline (speedup 1.0000x reference)
#include <cuda_runtime.h>

// Problem constants (fixed by the reference)
#define BB 8
#define TT 2048
#define CC 1024
#define HH 64
#define MM (BB * TT)   // 16384 rows

// Scratch: projected Q, K, V  (4 MB each) — __device__ globals per allocation rules
__device__ float g_Q[MM * HH];
__device__ float g_K[MM * HH];
__device__ float g_V[MM * HH];

// ---------------------------------------------------------------------------
// Projection GEMM: C(16384 x 64) = x(16384 x 1024) @ W(1024 x 64), for 3 Ws.
// 64x64 tile per block, BK=16, 256 threads, 4x4 micro-tile per thread.
// ---------------------------------------------------------------------------
__global__ __launch_bounds__(256) void proj_kernel(
    const float* __restrict__ x,
    const float* __restrict__ Wk,
    const float* __restrict__ Wq,
    const float* __restrict__ Wv)
{
    __shared__ float As[16][68];   // [k][row], padded to dodge STS transpose conflicts
    __shared__ float Bs[16][64];   // [k][n]

    const float* W  = (blockIdx.y == 0) ? Wk : ((blockIdx.y == 1) ? Wq : Wv);
    float*       Out = (blockIdx.y == 0) ? g_K : ((blockIdx.y == 1) ? g_Q : g_V);

    const int tid = threadIdx.x;
    const int tx  = tid & 15;      // 0..15  -> N
    const int ty  = tid >> 4;      // 0..15  -> M
    const int row0 = blockIdx.x * 64;

    float acc[4][4] = {};

    for (int k0 = 0; k0 < CC; k0 += 16) {
        // Load A tile: 64 rows x 16 k.  One float4 per thread, transposed into As[k][row].
        {
            const int r  = tid >> 2;          // 0..63
            const int kc = (tid & 3) * 4;     // 0,4,8,12
            float4 v = *(const float4*)(x + (size_t)(row0 + r) * CC + k0 + kc);
            As[kc + 0][r] = v.x;
            As[kc + 1][r] = v.y;
            As[kc + 2][r] = v.z;
            As[kc + 3][r] = v.w;
        }
        // Load B tile: 16 k x 64 n.  One float4 per thread, direct layout.
        {
            const int kr = tid >> 4;          // 0..15
            const int nc = (tid & 15) * 4;    // 0..60
            *(float4*)&Bs[kr][nc] = *(const float4*)(W + (size_t)(k0 + kr) * HH + nc);
        }
        __syncthreads();

        #pragma unroll
        for (int kk = 0; kk < 16; kk++) {
            float a[4], b[4];
            *(float4*)a = *(const float4*)&As[kk][ty * 4];
            *(float4*)b = *(const float4*)&Bs[kk][tx * 4];
            #pragma unroll
            for (int r = 0; r < 4; r++)
                #pragma unroll
                for (int c = 0; c < 4; c++)
                    acc[r][c] += a[r] * b[c];
        }
        __syncthreads();
    }

    #pragma unroll
    for (int r = 0; r < 4; r++)
        *(float4*)(Out + (size_t)(row0 + ty * 4 + r) * HH + tx * 4) = *(float4*)acc[r];
}

// ---------------------------------------------------------------------------
// Causal flash attention: 1 thread = 1 query row.  128 queries per block.
// K/V staged through shared in 32-key tiles; online softmax w/ lazy rescale.
// ---------------------------------------------------------------------------
__global__ __launch_bounds__(128) void attn_kernel(float* __restrict__ out)
{
    __shared__ float Ksh[32][64];
    __shared__ float Vsh[32][64];

    const int blocks_per_b = TT / 128;           // 16
    const int b   = blockIdx.x / blocks_per_b;
    const int q0  = (blockIdx.x % blocks_per_b) * 128;
    const int tid = threadIdx.x;
    const int i   = q0 + tid;                    // this thread's query index

    const float* Qrow = g_Q + ((size_t)b * TT + i) * HH;
    float q[HH];
    #pragma unroll
    for (int d = 0; d < HH; d += 4)
        *(float4*)&q[d] = *(const float4*)&Qrow[d];

    float o[HH];
    #pragma unroll
    for (int d = 0; d < HH; d++) o[d] = 0.f;

    float m = -1e30f;
    float l = 0.f;
    const float scale = 0.125f;                  // 1/sqrt(64)

    const int nkeys = q0 + 128;                  // block covers keys [0, q0+127]
    const float* Kbase = g_K + (size_t)b * TT * HH;
    const float* Vbase = g_V + (size_t)b * TT * HH;

    for (int j0 = 0; j0 < nkeys; j0 += 32) {
        // Stage 32 keys + 32 values (2048 floats each = 512 float4; 4 per thread)
        #pragma unroll
        for (int it = 0; it < 4; it++) {
            const int slot = tid + it * 128;     // 0..511
            const int kr   = slot >> 4;          // key row 0..31
            const int dc   = (slot & 15) * 4;    // dim col
            *(float4*)&Ksh[kr][dc] = *(const float4*)(Kbase + (size_t)(j0 + kr) * HH + dc);
            *(float4*)&Vsh[kr][dc] = *(const float4*)(Vbase + (size_t)(j0 + kr) * HH + dc);
        }
        __syncthreads();

        const int jmax = min(32, i - j0 + 1);    // causal: keys j0+jj with jj < jmax
        for (int jj = 0; jj < jmax; jj++) {
            // s = scale * dot(q, K[jj])
            float sp0 = 0.f, sp1 = 0.f, sp2 = 0.f, sp3 = 0.f;
            #pragma unroll
            for (int d = 0; d < HH; d += 4) {
                float4 kv = *(const float4*)&Ksh[jj][d];
                sp0 += q[d + 0] * kv.x;
                sp1 += q[d + 1] * kv.y;
                sp2 += q[d + 2] * kv.z;
                sp3 += q[d + 3] * kv.w;
            }
            const float s = ((sp0 + sp1) + (sp2 + sp3)) * scale;

            if (s > m) {                         // rare: rescale running state
                const float alpha = __expf(m - s);
                l *= alpha;
                #pragma unroll
                for (int d = 0; d < HH; d++) o[d] *= alpha;
                m = s;
            }
            const float p = __expf(s - m);
            l += p;
            #pragma unroll
            for (int d = 0; d < HH; d += 4) {
                float4 vv = *(const float4*)&Vsh[jj][d];
                o[d + 0] += p * vv.x;
                o[d + 1] += p * vv.y;
                o[d + 2] += p * vv.z;
                o[d + 3] += p * vv.w;
            }
        }
        __syncthreads();
    }

    const float inv = 1.f / l;
    float* Orow = out + ((size_t)b * TT + i) * HH;
    #pragma unroll
    for (int d = 0; d < HH; d += 4) {
        float4 v;
        v.x = o[d + 0] * inv;
        v.y = o[d + 1] * inv;
        v.z = o[d + 2] * inv;
        v.w = o[d + 3] * inv;
        *(float4*)&Orow[d] = v;
    }
}

// ---------------------------------------------------------------------------
extern "C" void kernel_launch(void* const* d_in, const int* in_sizes, int n_in,
                              void* d_out, int out_size)
{
    const float* x  = (const float*)d_in[0];
    const float* Wk = (const float*)d_in[1];
    const float* Wq = (const float*)d_in[2];
    const float* Wv = (const float*)d_in[3];
    float* out = (float*)d_out;

    dim3 pgrid(MM / 64, 3);
    proj_kernel<<<pgrid, 256>>>(x, Wk, Wq, Wv);

    attn_kernel<<<BB * (TT / 128), 128>>>(out);
}

// round 5
// speedup vs baseline: 1.8192x; 1.8192x over previous
#include <cuda_runtime.h>

// Problem constants (fixed by the reference)
#define BB 8
#define TT 2048
#define CC 1024
#define HH 64
#define MM (BB * TT)   // 16384 rows

// Scratch: projected Q, K, V  (4 MB each) — __device__ globals per allocation rules
__device__ float g_Q[MM * HH];
__device__ float g_K[MM * HH];
__device__ float g_V[MM * HH];

// ---------------------------------------------------------------------------
// Projection GEMM: C(16384 x 64) = x(16384 x 1024) @ W(1024 x 64), for 3 Ws.
// 64x64 tile per block, BK=16, 256 threads, 4x4 micro-tile per thread.
// (Already at fp32 FFMA roofline — unchanged this round.)
// ---------------------------------------------------------------------------
__global__ __launch_bounds__(256) void proj_kernel(
    const float* __restrict__ x,
    const float* __restrict__ Wk,
    const float* __restrict__ Wq,
    const float* __restrict__ Wv)
{
    __shared__ float As[16][68];   // [k][row]
    __shared__ float Bs[16][64];   // [k][n]

    const float* W  = (blockIdx.y == 0) ? Wk : ((blockIdx.y == 1) ? Wq : Wv);
    float*       Out = (blockIdx.y == 0) ? g_K : ((blockIdx.y == 1) ? g_Q : g_V);

    const int tid = threadIdx.x;
    const int tx  = tid & 15;
    const int ty  = tid >> 4;
    const int row0 = blockIdx.x * 64;

    float acc[4][4] = {};

    for (int k0 = 0; k0 < CC; k0 += 16) {
        {
            const int r  = tid >> 2;
            const int kc = (tid & 3) * 4;
            float4 v = *(const float4*)(x + (size_t)(row0 + r) * CC + k0 + kc);
            As[kc + 0][r] = v.x;
            As[kc + 1][r] = v.y;
            As[kc + 2][r] = v.z;
            As[kc + 3][r] = v.w;
        }
        {
            const int kr = tid >> 4;
            const int nc = (tid & 15) * 4;
            *(float4*)&Bs[kr][nc] = *(const float4*)(W + (size_t)(k0 + kr) * HH + nc);
        }
        __syncthreads();

        #pragma unroll
        for (int kk = 0; kk < 16; kk++) {
            float a[4], b[4];
            *(float4*)a = *(const float4*)&As[kk][ty * 4];
            *(float4*)b = *(const float4*)&Bs[kk][tx * 4];
            #pragma unroll
            for (int r = 0; r < 4; r++)
                #pragma unroll
                for (int c = 0; c < 4; c++)
                    acc[r][c] += a[r] * b[c];
        }
        __syncthreads();
    }

    #pragma unroll
    for (int r = 0; r < 4; r++)
        *(float4*)(Out + (size_t)(row0 + ty * 4 + r) * HH + tx * 4) = *(float4*)acc[r];
}

// ---------------------------------------------------------------------------
// Flash attention v2: block = 64 queries, 256 threads (16x16 grid, 4x4 tiles).
// Per 64-key tile:  S = Q·K^T (smem GEMM) -> shuffle row-reduce online softmax
// (base-2, scale folded into Q) -> P via smem -> O += P·V (smem GEMM).
// Heavy-first block order for the causal triangle.
// ---------------------------------------------------------------------------
#define QS_STRIDE 68
#define PS_STRIDE 68

__global__ __launch_bounds__(256) void attn_kernel(float* __restrict__ out)
{
    extern __shared__ float sm[];
    float (*Qs)[QS_STRIDE] = (float (*)[QS_STRIDE])sm;                       // [d][row]
    float (*Ks)[QS_STRIDE] = (float (*)[QS_STRIDE])(sm + 64 * QS_STRIDE);    // [d][col]
    float (*Vs)[64]        = (float (*)[64])(sm + 2 * 64 * QS_STRIDE);       // [k][d]
    float (*Ps)[PS_STRIDE] = (float (*)[PS_STRIDE])(sm + 2 * 64 * QS_STRIDE + 64 * 64); // [row][k]

    const int tid = threadIdx.x;
    const int tx  = tid & 15;           // -> key cols / out dims (x4)
    const int ty  = tid >> 4;           // -> query rows (x4)

    const int b  = blockIdx.x & 7;
    const int qt = 31 - (blockIdx.x >> 3);     // heavy tiles launch first
    const int q0 = qt * 64;

    const float* Qg = g_Q + ((size_t)b * TT + q0) * HH;
    const float* Kg = g_K + (size_t)b * TT * HH;
    const float* Vg = g_V + (size_t)b * TT * HH;

    // fold softmax scale and log2(e) into Q so the inner softmax is pure exp2
    const float qscale = 0.125f * 1.44269504f;

    // Load Q tile transposed ([d][row]) and pre-scaled
    #pragma unroll
    for (int it = 0; it < 4; it++) {
        const int i  = tid + it * 256;          // 0..1023
        const int r  = i >> 4;                  // row 0..63
        const int dc = (i & 15) * 4;            // d col
        float4 v = *(const float4*)(Qg + (size_t)r * HH + dc);
        Qs[dc + 0][r] = v.x * qscale;
        Qs[dc + 1][r] = v.y * qscale;
        Qs[dc + 2][r] = v.z * qscale;
        Qs[dc + 3][r] = v.w * qscale;
    }

    float o[4][4] = {};
    float m[4], l[4];
    #pragma unroll
    for (int r = 0; r < 4; r++) { m[r] = -1e30f; l[r] = 0.f; }

    for (int j0 = 0; j0 <= q0; j0 += 64) {
        __syncthreads();   // previous iter's Ks/Vs/Ps readers done

        // Stage K (transposed) and V (natural) tiles
        #pragma unroll
        for (int it = 0; it < 4; it++) {
            const int i  = tid + it * 256;
            const int r  = i >> 4;
            const int dc = (i & 15) * 4;
            float4 kv = *(const float4*)(Kg + (size_t)(j0 + r) * HH + dc);
            Ks[dc + 0][r] = kv.x;
            Ks[dc + 1][r] = kv.y;
            Ks[dc + 2][r] = kv.z;
            Ks[dc + 3][r] = kv.w;
            *(float4*)&Vs[r][dc] = *(const float4*)(Vg + (size_t)(j0 + r) * HH + dc);
        }
        __syncthreads();

        // S tile: s[r][c] = qscale * q_row · k_col
        float s[4][4] = {};
        #pragma unroll
        for (int d = 0; d < 64; d++) {
            float a[4], bv[4];
            *(float4*)a  = *(const float4*)&Qs[d][ty * 4];   // broadcast in half-warp
            *(float4*)bv = *(const float4*)&Ks[d][tx * 4];
            #pragma unroll
            for (int r = 0; r < 4; r++)
                #pragma unroll
                for (int c = 0; c < 4; c++)
                    s[r][c] += a[r] * bv[c];
        }

        // Causal mask (only the diagonal tile needs it)
        if (j0 == q0) {
            #pragma unroll
            for (int r = 0; r < 4; r++)
                #pragma unroll
                for (int c = 0; c < 4; c++)
                    if (tx * 4 + c > ty * 4 + r) s[r][c] = -1e30f;
        }

        // Online softmax, per query row (16 lanes of a half-warp share a row group)
        #pragma unroll
        for (int r = 0; r < 4; r++) {
            float mx = fmaxf(fmaxf(s[r][0], s[r][1]), fmaxf(s[r][2], s[r][3]));
            mx = fmaxf(mx, __shfl_xor_sync(0xffffffffu, mx, 1));
            mx = fmaxf(mx, __shfl_xor_sync(0xffffffffu, mx, 2));
            mx = fmaxf(mx, __shfl_xor_sync(0xffffffffu, mx, 4));
            mx = fmaxf(mx, __shfl_xor_sync(0xffffffffu, mx, 8));

            const float mnew  = fmaxf(m[r], mx);
            const float alpha = exp2f(m[r] - mnew);
            m[r] = mnew;

            float psum = 0.f;
            #pragma unroll
            for (int c = 0; c < 4; c++) {
                const float p = exp2f(s[r][c] - mnew);
                s[r][c] = p;
                psum += p;
            }
            psum += __shfl_xor_sync(0xffffffffu, psum, 1);
            psum += __shfl_xor_sync(0xffffffffu, psum, 2);
            psum += __shfl_xor_sync(0xffffffffu, psum, 4);
            psum += __shfl_xor_sync(0xffffffffu, psum, 8);

            l[r] = l[r] * alpha + psum;
            #pragma unroll
            for (int c = 0; c < 4; c++) o[r][c] *= alpha;
        }

        // Stage P ([row][k]) for the PV GEMM
        #pragma unroll
        for (int r = 0; r < 4; r++)
            *(float4*)&Ps[ty * 4 + r][tx * 4] = *(float4*)s[r];
        __syncthreads();

        // O += P · V
        #pragma unroll
        for (int k = 0; k < 64; k++) {
            float bv[4];
            *(float4*)bv = *(const float4*)&Vs[k][tx * 4];
            const float a0 = Ps[ty * 4 + 0][k];   // 2-addr broadcast reads
            const float a1 = Ps[ty * 4 + 1][k];
            const float a2 = Ps[ty * 4 + 2][k];
            const float a3 = Ps[ty * 4 + 3][k];
            #pragma unroll
            for (int c = 0; c < 4; c++) {
                o[0][c] += a0 * bv[c];
                o[1][c] += a1 * bv[c];
                o[2][c] += a2 * bv[c];
                o[3][c] += a3 * bv[c];
            }
        }
    }

    // Normalize and write out
    float* Orow = out + ((size_t)b * TT + q0) * HH;
    #pragma unroll
    for (int r = 0; r < 4; r++) {
        const float inv = 1.f / l[r];
        float4 v;
        v.x = o[r][0] * inv;
        v.y = o[r][1] * inv;
        v.z = o[r][2] * inv;
        v.w = o[r][3] * inv;
        *(float4*)(Orow + (size_t)(ty * 4 + r) * HH + tx * 4) = v;
    }
}

// ---------------------------------------------------------------------------
extern "C" void kernel_launch(void* const* d_in, const int* in_sizes, int n_in,
                              void* d_out, int out_size)
{
    const float* x  = (const float*)d_in[0];
    const float* Wk = (const float*)d_in[1];
    const float* Wq = (const float*)d_in[2];
    const float* Wv = (const float*)d_in[3];
    float* out = (float*)d_out;

    // 2*64*68 + 64*64 + 64*68 floats = 68608 bytes of dynamic smem
    const int smem_bytes = (2 * 64 * QS_STRIDE + 64 * 64 + 64 * PS_STRIDE) * (int)sizeof(float);
    cudaFuncSetAttribute(attn_kernel, cudaFuncAttributeMaxDynamicSharedMemorySize, smem_bytes);

    dim3 pgrid(MM / 64, 3);
    proj_kernel<<<pgrid, 256>>>(x, Wk, Wq, Wv);

    attn_kernel<<<BB * (TT / 64), 256, smem_bytes>>>(out);
}

// round 6
// speedup vs baseline: 2.0177x; 1.1091x over previous
#include <cuda_runtime.h>

// Problem constants (fixed by the reference)
#define BB 8
#define TT 2048
#define CC 1024
#define HH 64
#define MM (BB * TT)   // 16384 rows

// Scratch: projected Q, K, V  (4 MB each) — __device__ globals per allocation rules
__device__ float g_Q[MM * HH];
__device__ float g_K[MM * HH];
__device__ float g_V[MM * HH];

// ---------------------------------------------------------------------------
// Projection GEMM: C(16384 x 64) = x(16384 x 1024) @ W(1024 x 64), for 3 Ws.
// 128x64 tile per block, BK=16, 256 threads, 8x4 micro-tile per thread.
// ---------------------------------------------------------------------------
__global__ __launch_bounds__(256) void proj_kernel(
    const float* __restrict__ x,
    const float* __restrict__ Wk,
    const float* __restrict__ Wq,
    const float* __restrict__ Wv)
{
    __shared__ float As[16][132];   // [k][row], 128 rows + pad
    __shared__ float Bs[16][64];    // [k][n]

    const float* W  = (blockIdx.y == 0) ? Wk : ((blockIdx.y == 1) ? Wq : Wv);
    float*       Out = (blockIdx.y == 0) ? g_K : ((blockIdx.y == 1) ? g_Q : g_V);

    const int tid = threadIdx.x;
    const int tx  = tid & 15;       // n:  tx*4
    const int ty  = tid >> 4;       // m:  ty*8 (0..15 -> 128 rows)
    const int row0 = blockIdx.x * 128;

    float acc[8][4] = {};

    for (int k0 = 0; k0 < CC; k0 += 16) {
        // A tile: 128 rows x 16 k -> transposed As[k][row]. 2 float4 per thread.
        #pragma unroll
        for (int it = 0; it < 2; it++) {
            const int r  = (tid >> 2) + it * 64;   // 0..127
            const int kc = (tid & 3) * 4;
            float4 v = *(const float4*)(x + (size_t)(row0 + r) * CC + k0 + kc);
            As[kc + 0][r] = v.x;
            As[kc + 1][r] = v.y;
            As[kc + 2][r] = v.z;
            As[kc + 3][r] = v.w;
        }
        // B tile: 16 k x 64 n, 1 float4 per thread.
        {
            const int kr = tid >> 4;
            const int nc = (tid & 15) * 4;
            *(float4*)&Bs[kr][nc] = *(const float4*)(W + (size_t)(k0 + kr) * HH + nc);
        }
        __syncthreads();

        #pragma unroll
        for (int kk = 0; kk < 16; kk++) {
            float a[8], b[4];
            *(float4*)&a[0] = *(const float4*)&As[kk][ty * 8];
            *(float4*)&a[4] = *(const float4*)&As[kk][ty * 8 + 4];
            *(float4*)b     = *(const float4*)&Bs[kk][tx * 4];
            #pragma unroll
            for (int r = 0; r < 8; r++)
                #pragma unroll
                for (int c = 0; c < 4; c++)
                    acc[r][c] += a[r] * b[c];
        }
        __syncthreads();
    }

    #pragma unroll
    for (int r = 0; r < 8; r++)
        *(float4*)(Out + (size_t)(row0 + ty * 8 + r) * HH + tx * 4) = *(float4*)acc[r];
}

// ---------------------------------------------------------------------------
// Flash attention v3: block = 32 queries x 64-key tiles, 128 threads
// (16x8 grid, 4x4 micro-tiles).  512 blocks -> ~3.5 blocks/SM resident.
// Base-2 online softmax with scale folded into Q; PV k-unrolled x4.
// ---------------------------------------------------------------------------
#define QT 32
#define KT 64
#define QS_STRIDE 36
#define KS_STRIDE 68
#define PS_STRIDE 68

#define SM_QS 0
#define SM_KS (SM_QS + 64 * QS_STRIDE)
#define SM_VS (SM_KS + 64 * KS_STRIDE)
#define SM_PS (SM_VS + 64 * 64)
#define SM_TOTAL (SM_PS + QT * PS_STRIDE)     // 12928 floats = 51712 bytes

__global__ __launch_bounds__(128) void attn_kernel(float* __restrict__ out)
{
    extern __shared__ float sm[];
    float (*Qs)[QS_STRIDE] = (float (*)[QS_STRIDE])(sm + SM_QS);   // [d][qrow]
    float (*Ks)[KS_STRIDE] = (float (*)[KS_STRIDE])(sm + SM_KS);   // [d][kcol]
    float (*Vs)[64]        = (float (*)[64])(sm + SM_VS);          // [k][d]
    float (*Ps)[PS_STRIDE] = (float (*)[PS_STRIDE])(sm + SM_PS);   // [qrow][k]

    const int tid = threadIdx.x;
    const int tx  = tid & 15;            // key cols / out dims (x4)
    const int ty  = tid >> 4;            // 0..7 -> query rows (x4)

    const int b  = blockIdx.x & 7;
    const int qt = (TT / QT - 1) - (blockIdx.x >> 3);   // heavy tiles first
    const int q0 = qt * QT;

    const float* Qg = g_Q + ((size_t)b * TT + q0) * HH;
    const float* Kg = g_K + (size_t)b * TT * HH;
    const float* Vg = g_V + (size_t)b * TT * HH;

    // fold softmax scale and log2(e) into Q so the inner softmax is pure exp2
    const float qscale = 0.125f * 1.44269504f;

    // Load Q tile transposed ([d][row]) and pre-scaled: 512 float4, 4/thread
    #pragma unroll
    for (int it = 0; it < 4; it++) {
        const int i  = tid + it * 128;          // 0..511
        const int r  = i >> 4;                  // 0..31
        const int dc = (i & 15) * 4;
        float4 v = *(const float4*)(Qg + (size_t)r * HH + dc);
        Qs[dc + 0][r] = v.x * qscale;
        Qs[dc + 1][r] = v.y * qscale;
        Qs[dc + 2][r] = v.z * qscale;
        Qs[dc + 3][r] = v.w * qscale;
    }

    float o[4][4] = {};
    float m[4], l[4];
    #pragma unroll
    for (int r = 0; r < 4; r++) { m[r] = -1e30f; l[r] = 0.f; }

    for (int j0 = 0; j0 < q0 + QT; j0 += KT) {
        __syncthreads();   // previous iter's Vs/Ps readers done

        // Stage K (transposed) and V (natural): 1024 float4 each, 8/thread
        #pragma unroll
        for (int it = 0; it < 8; it++) {
            const int i  = tid + it * 128;      // 0..1023
            const int r  = i >> 4;              // 0..63
            const int dc = (i & 15) * 4;
            float4 kv = *(const float4*)(Kg + (size_t)(j0 + r) * HH + dc);
            Ks[dc + 0][r] = kv.x;
            Ks[dc + 1][r] = kv.y;
            Ks[dc + 2][r] = kv.z;
            Ks[dc + 3][r] = kv.w;
            *(float4*)&Vs[r][dc] = *(const float4*)(Vg + (size_t)(j0 + r) * HH + dc);
        }
        __syncthreads();

        // S tile: s[r][c] = qscaled_q_row . k_col
        float s[4][4] = {};
        #pragma unroll
        for (int d = 0; d < 64; d++) {
            float a[4], bv[4];
            *(float4*)a  = *(const float4*)&Qs[d][ty * 4];
            *(float4*)bv = *(const float4*)&Ks[d][tx * 4];
            #pragma unroll
            for (int r = 0; r < 4; r++)
                #pragma unroll
                for (int c = 0; c < 4; c++)
                    s[r][c] += a[r] * bv[c];
        }

        // Causal mask: needed whenever this key tile can reach past a query
        if (j0 + KT > q0) {
            #pragma unroll
            for (int r = 0; r < 4; r++)
                #pragma unroll
                for (int c = 0; c < 4; c++)
                    if (j0 + tx * 4 + c > q0 + ty * 4 + r) s[r][c] = -1e30f;
        }

        // Online softmax per query row (16 lanes of a half-warp share rows)
        #pragma unroll
        for (int r = 0; r < 4; r++) {
            float mx = fmaxf(fmaxf(s[r][0], s[r][1]), fmaxf(s[r][2], s[r][3]));
            mx = fmaxf(mx, __shfl_xor_sync(0xffffffffu, mx, 1));
            mx = fmaxf(mx, __shfl_xor_sync(0xffffffffu, mx, 2));
            mx = fmaxf(mx, __shfl_xor_sync(0xffffffffu, mx, 4));
            mx = fmaxf(mx, __shfl_xor_sync(0xffffffffu, mx, 8));

            const float mnew  = fmaxf(m[r], mx);
            const float alpha = exp2f(m[r] - mnew);
            m[r] = mnew;

            float psum = 0.f;
            #pragma unroll
            for (int c = 0; c < 4; c++) {
                const float p = exp2f(s[r][c] - mnew);
                s[r][c] = p;
                psum += p;
            }
            psum += __shfl_xor_sync(0xffffffffu, psum, 1);
            psum += __shfl_xor_sync(0xffffffffu, psum, 2);
            psum += __shfl_xor_sync(0xffffffffu, psum, 4);
            psum += __shfl_xor_sync(0xffffffffu, psum, 8);

            l[r] = l[r] * alpha + psum;
            #pragma unroll
            for (int c = 0; c < 4; c++) o[r][c] *= alpha;
        }

        // Stage P ([row][k]) for the PV GEMM
        #pragma unroll
        for (int r = 0; r < 4; r++)
            *(float4*)&Ps[ty * 4 + r][tx * 4] = *(float4*)s[r];
        __syncthreads();

        // O += P . V   (k unrolled x4, all loads vectorized)
        #pragma unroll
        for (int k = 0; k < KT; k += 4) {
            float a[4][4], bv[4][4];
            #pragma unroll
            for (int r = 0; r < 4; r++)
                *(float4*)a[r] = *(const float4*)&Ps[ty * 4 + r][k];
            #pragma unroll
            for (int kk = 0; kk < 4; kk++)
                *(float4*)bv[kk] = *(const float4*)&Vs[k + kk][tx * 4];
            #pragma unroll
            for (int r = 0; r < 4; r++)
                #pragma unroll
                for (int kk = 0; kk < 4; kk++)
                    #pragma unroll
                    for (int c = 0; c < 4; c++)
                        o[r][c] += a[r][kk] * bv[kk][c];
        }
    }

    // Normalize and write out
    float* Orow = out + ((size_t)b * TT + q0) * HH;
    #pragma unroll
    for (int r = 0; r < 4; r++) {
        const float inv = 1.f / l[r];
        float4 v;
        v.x = o[r][0] * inv;
        v.y = o[r][1] * inv;
        v.z = o[r][2] * inv;
        v.w = o[r][3] * inv;
        *(float4*)(Orow + (size_t)(ty * 4 + r) * HH + tx * 4) = v;
    }
}

// ---------------------------------------------------------------------------
extern "C" void kernel_launch(void* const* d_in, const int* in_sizes, int n_in,
                              void* d_out, int out_size)
{
    const float* x  = (const float*)d_in[0];
    const float* Wk = (const float*)d_in[1];
    const float* Wq = (const float*)d_in[2];
    const float* Wv = (const float*)d_in[3];
    float* out = (float*)d_out;

    const int smem_bytes = SM_TOTAL * (int)sizeof(float);   // 51712
    cudaFuncSetAttribute(attn_kernel, cudaFuncAttributeMaxDynamicSharedMemorySize, smem_bytes);

    dim3 pgrid(MM / 128, 3);
    proj_kernel<<<pgrid, 256>>>(x, Wk, Wq, Wv);

    attn_kernel<<<BB * (TT / QT), 128, smem_bytes>>>(out);
}